// round 4
// baseline (speedup 1.0000x reference)
#include <cuda_runtime.h>
#include <cstdint>
#include <math.h>

// Problem constants (dataset: B=65536, D=256, K=10)
#define KK 10
#define DD 256
#define BT 128              // threads per block
#define RPB 256             // rows per block (2 per thread)
#define NCH 16              // d-chunks per row
#define CHD 16              // d per chunk (8 f32x2 pairs)
#define MARGIN 0.125f       // cheap-vs-exact logit gap threshold for exact recheck
#define L2PI_F 1.8378770664093453f
#define L2PI_D 1.8378770664093453

typedef unsigned long long ull;

// ---------- packed f32x2 helpers ----------
static __device__ __forceinline__ ull pack2(float x, float y) {
    ull r; asm("mov.b64 %0, {%1, %2};" : "=l"(r) : "f"(x), "f"(y)); return r;
}
static __device__ __forceinline__ void unpack2(ull v, float& x, float& y) {
    asm("mov.b64 {%0, %1}, %2;" : "=f"(x), "=f"(y) : "l"(v));
}
static __device__ __forceinline__ ull fma2(ull a, ull b, ull c) {
    ull d; asm("fma.rn.f32x2 %0, %1, %2, %3;" : "=l"(d) : "l"(a), "l"(b), "l"(c)); return d;
}

// ================= single fused kernel =================
__global__ void __launch_bounds__(BT)
k_all(const float* __restrict__ q, const float* __restrict__ mu,
      const float* __restrict__ lv,
      float* __restrict__ out_logit, float* __restrict__ out_qy,
      float* __restrict__ out_ind, int nrows)
{
    // coef table: [k][d-pair] -> (cA pair, cB pair) adjacent for one LDS.128
    __shared__ __align__(16) ull s_cf[KK][DD / 2][2];   // 20480 B
    __shared__ double s_Cp[KK][8];
    __shared__ float  s_C[KK];
    __shared__ float  s_logk;
    __shared__ int    s_list[RPB];
    __shared__ int    s_cnt;

    int t = threadIdx.x;
    if (t == 0) {
        s_cnt  = 0;
        s_logk = (float)log((double)(1.0f / (float)KK));   // round-3 logk, bit-for-bit
    }

    // ---- per-block prep: cheap coefficients (tolerant path, any rounding) ----
    // llh_d = -0.5*iv*q^2 + iv*mu*q + (-0.5*iv*mu^2 - 0.5*(lv+L2PI)), iv = e^-lv
    for (int i = t; i < KK * DD / 2; i += BT) {
        int k = i / (DD / 2), p = i % (DD / 2), d = 2 * p;
        float l0 = lv[k * DD + d], l1 = lv[k * DD + d + 1];
        float m0 = mu[k * DD + d], m1 = mu[k * DD + d + 1];
        float i0 = expf(-l0), i1 = expf(-l1);
        s_cf[k][p][0] = pack2(-0.5f * i0, -0.5f * i1);   // cA
        s_cf[k][p][1] = pack2(i0 * m0,    i1 * m1);      // cB
    }
    if (t < 80) {   // C_k partials in fp64 (deterministic tree)
        int k = t >> 3, part = t & 7;
        double s = 0.0;
        for (int j = 0; j < 32; j++) {
            int d = part * 32 + j;
            double l = (double)lv[k * DD + d];
            double m = (double)mu[k * DD + d];
            double iv = exp(-l);
            s += -0.5 * iv * m * m - 0.5 * (l + L2PI_D);
        }
        s_Cp[k][part] = s;
    }
    __syncthreads();
    if (t < KK) {
        double tot = 0.0;
        #pragma unroll
        for (int j = 0; j < 8; j++) tot += s_Cp[t][j];
        s_C[t] = (float)tot + s_logk;
    }
    __syncthreads();

    // ---- cheap logits: 2 rows/thread, Horner packed FFMA ----
    int row0 = blockIdx.x * RPB;
    int rA = row0 + t, rB = row0 + t + BT;

    ull acc[2][KK];
    #pragma unroll
    for (int r = 0; r < 2; r++)
        #pragma unroll
        for (int k = 0; k < KK; k++) acc[r][k] = 0ull;   // (+0.f,+0.f)

    for (int c = 0; c < NCH; c++) {
        ull qv[2][8];
        #pragma unroll
        for (int r = 0; r < 2; r++) {
            int row = (r == 0) ? rA : rB;
            float4 a = make_float4(0.f,0.f,0.f,0.f), b = a, cc = a, dd = a;
            if (row < nrows) {
                const float4* p4 = reinterpret_cast<const float4*>(
                    q + (size_t)row * DD + c * CHD);
                a = p4[0]; b = p4[1]; cc = p4[2]; dd = p4[3];
            }
            qv[r][0] = pack2(a.x,  a.y);  qv[r][1] = pack2(a.z,  a.w);
            qv[r][2] = pack2(b.x,  b.y);  qv[r][3] = pack2(b.z,  b.w);
            qv[r][4] = pack2(cc.x, cc.y); qv[r][5] = pack2(cc.z, cc.w);
            qv[r][6] = pack2(dd.x, dd.y); qv[r][7] = pack2(dd.z, dd.w);
        }
        #pragma unroll
        for (int k = 0; k < KK; k++) {
            #pragma unroll
            for (int p = 0; p < 8; p++) {
                ulonglong2 cf = *reinterpret_cast<const ulonglong2*>(
                    &s_cf[k][c * 8 + p][0]);       // one LDS.128: (cA, cB)
                #pragma unroll
                for (int r = 0; r < 2; r++) {
                    ull h = fma2(cf.x, qv[r][p], cf.y);   // cA*q + cB
                    acc[r][k] = fma2(h, qv[r][p], acc[r][k]);
                }
            }
        }
    }

    // ---- fused finish (cheap, tolerant) + near-tie flagging ----
    #pragma unroll
    for (int r = 0; r < 2; r++) {
        int row = (r == 0) ? rA : rB;
        if (row < nrows) {
            float l[KK];
            #pragma unroll
            for (int k = 0; k < KK; k++) {
                float lo, hi; unpack2(acc[r][k], lo, hi);
                l[k] = (lo + hi) + s_C[k];
            }
            float t1 = l[0], t2 = -3.4e38f;
            #pragma unroll
            for (int k = 1; k < KK; k++) {
                float v = l[k];
                if (v > t1) { t2 = t1; t1 = v; } else if (v > t2) t2 = v;
            }
            float e[KK], ssum = 0.0f;
            #pragma unroll
            for (int k = 0; k < KK; k++) { e[k] = __expf(l[k] - t1); ssum += e[k]; }
            float inv = 1.0f / ssum;

            float2* lo2 = reinterpret_cast<float2*>(out_logit + (size_t)row * KK);
            float2* qo2 = reinterpret_cast<float2*>(out_qy    + (size_t)row * KK);
            #pragma unroll
            for (int i = 0; i < KK / 2; i++) {
                lo2[i] = make_float2(l[2*i], l[2*i+1]);
                qo2[i] = make_float2(e[2*i] * inv, e[2*i+1] * inv);
            }
            int best = 0; float bv = l[0];
            #pragma unroll
            for (int k = 1; k < KK; k++) if (l[k] > bv) { bv = l[k]; best = k; }
            out_ind[row] = (float)best;

            if (t1 - t2 < MARGIN) {          // near-tie: needs exact recompute
                int ix = atomicAdd(&s_cnt, 1);
                s_list[ix] = row;
            }
        }
    }
    __syncthreads();

    // ---- exact fix: warp-cooperative bitwise XLA:GPU emulation (round-3 order) ----
    int wid = t >> 5, lane = t & 31;
    int cnt = s_cnt;
    float logk = s_logk;
    for (int i = wid; i < cnt; i += BT / 32) {
        int row = s_list[i];
        float l10[KK];
        #pragma unroll 1
        for (int k = 0; k < KK; k++) {
            float W[4];
            #pragma unroll
            for (int j = 0; j < 4; j++) {
                int d0 = 64 * j + 2 * lane;
                float2 qq = *reinterpret_cast<const float2*>(q + (size_t)row * DD + d0);
                float m0 = mu[k * DD + d0], m1 = mu[k * DD + d0 + 1];
                float v0 = lv[k * DD + d0], v1 = lv[k * DD + d0 + 1];
                float e0 = (v0 == 0.0f) ? 1.0f : expf(v0);
                float e1 = (v1 == 0.0f) ? 1.0f : expf(v1);
                float f0 = __fadd_rn(qq.x, -m0);
                float f1 = __fadd_rn(qq.y, -m1);
                // u = fl(fl(fl(fl(diff^2)/e^lv) + lv) + L2PI); for lv==0 this is
                // bitwise identical to round 3's fast chain fl(fl(diff^2)+L2PI)
                float u0 = __fadd_rn(__fadd_rn(__fdiv_rn(__fmul_rn(f0, f0), e0), v0), L2PI_F);
                float u1 = __fadd_rn(__fadd_rn(__fdiv_rn(__fmul_rn(f1, f1), e1), v1), L2PI_F);
                float s = __fadd_rn(u0, u1);          // s_t = fl(u_even + u_odd)
                s = __fadd_rn(s, __shfl_down_sync(0xffffffffu, s, 16));
                s = __fadd_rn(s, __shfl_down_sync(0xffffffffu, s, 8));
                s = __fadd_rn(s, __shfl_down_sync(0xffffffffu, s, 4));
                s = __fadd_rn(s, __shfl_down_sync(0xffffffffu, s, 2));
                s = __fadd_rn(s, __shfl_down_sync(0xffffffffu, s, 1));
                W[j] = __shfl_sync(0xffffffffu, s, 0);
            }
            float L = __fadd_rn(__fadd_rn(W[0], W[2]), __fadd_rn(W[1], W[3]));
            l10[k] = __fadd_rn(__fmul_rn(-0.5f, L), logk);
        }
        if (lane == 0) {
            // exact round-3 finish
            float m = l10[0];
            #pragma unroll
            for (int k = 1; k < KK; k++) m = fmaxf(m, l10[k]);
            float e[KK];
            #pragma unroll
            for (int k = 0; k < KK; k++) e[k] = expf(__fadd_rn(l10[k], -m));
            float s0 = __fadd_rn(__fadd_rn(__fadd_rn(e[0], e[8]), e[4]),
                                 __fadd_rn(e[2], e[6]));
            float s1 = __fadd_rn(__fadd_rn(__fadd_rn(e[1], e[9]), e[5]),
                                 __fadd_rn(e[3], e[7]));
            float ssum = __fadd_rn(s0, s1);
            float qv[KK];
            #pragma unroll
            for (int k = 0; k < KK; k++) qv[k] = __fdiv_rn(e[k], ssum);
            #pragma unroll
            for (int k = 0; k < KK; k++) {
                out_logit[(size_t)row * KK + k] = l10[k];
                out_qy   [(size_t)row * KK + k] = qv[k];
            }
            int best = 0; float bv = qv[0];
            #pragma unroll
            for (int k = 1; k < KK; k++)
                if (qv[k] > bv) { bv = qv[k]; best = k; }
            out_ind[row] = (float)best;
        }
    }
}

extern "C" void kernel_launch(void* const* d_in, const int* in_sizes, int n_in,
                              void* d_out, int out_size) {
    const float* q_z = (const float*)d_in[0];   // [B, 256]
    const float* mu  = (const float*)d_in[1];   // [10, 256]
    const float* lv  = (const float*)d_in[2];   // [10, 256]

    int nrows = in_sizes[0] / DD;

    float* out_logit = (float*)d_out;                    // [B, 10]
    float* out_qy    = out_logit + (size_t)nrows * KK;   // [B, 10]
    float* out_ind   = out_qy    + (size_t)nrows * KK;   // [B]

    int grid = (nrows + RPB - 1) / RPB;                  // 256 blocks -> single wave
    k_all<<<grid, BT>>>(q_z, mu, lv, out_logit, out_qy, out_ind, nrows);
}

// round 5
// speedup vs baseline: 2.3130x; 2.3130x over previous
#include <cuda_runtime.h>
#include <cstdint>
#include <math.h>

// Problem constants (dataset: B=65536, D=256, K=10)
#define KK 10
#define DD 256
#define BT 128               // threads per block = rows per block (1 row/thread)
#define NCH 8                // d-chunks per row
#define CHD 32               // d per chunk (16 f32x2 pairs)
#define MARGIN 0.03f         // cheap top-2 gap below which we run exact recheck
#define L2PI_F 1.8378770664093453f

typedef unsigned long long ull;

// ---------- packed f32x2 helpers ----------
static __device__ __forceinline__ ull pack2(float x, float y) {
    ull r; asm("mov.b64 %0, {%1, %2};" : "=l"(r) : "f"(x), "f"(y)); return r;
}
static __device__ __forceinline__ void unpack2(ull v, float& x, float& y) {
    asm("mov.b64 {%0, %1}, %2;" : "=f"(x), "=f"(y) : "l"(v));
}
static __device__ __forceinline__ ull fma2(ull a, ull b, ull c) {
    ull d; asm("fma.rn.f32x2 %0, %1, %2, %3;" : "=l"(d) : "l"(a), "l"(b), "l"(c)); return d;
}

// ================= single fused kernel =================
__global__ void __launch_bounds__(BT)
k_all(const float* __restrict__ q, const float* __restrict__ mu,
      const float* __restrict__ lv,
      float* __restrict__ out_logit, float* __restrict__ out_qy,
      float* __restrict__ out_ind, int nrows)
{
    // cB table: [pair][kpair][k&1] = -2*e^{-lv}*mu packed over (d,d+1); 10240 B
    __shared__ __align__(16) ull s_cb[128][5][2];
    // double-buffered q staging: [buf][d][row], +1 pad word -> conflict-free
    __shared__ float s_qf[2][CHD][BT + 1];              // 33024 B
    __shared__ float s_Cpart[KK][8];
    __shared__ float s_C[KK];
    __shared__ int   s_list[BT];
    __shared__ int   s_cnt, s_nz;

    const int t    = threadIdx.x;
    const int row0 = blockIdx.x * BT;
    const int row  = row0 + t;
    const float logk = (float)log((double)(1.0f / (float)KK));  // round-3 bits

    if (t == 0) { s_cnt = 0; s_nz = 0; }
    __syncthreads();

    // ---- prep: cB coefficients + C_k partials (fp32, fixed deterministic order) ----
    for (int i = t; i < KK * 128; i += BT) {          // 10 iters
        int k = i >> 7, p = i & 127, d = 2 * p;
        float l0 = lv[k * DD + d], l1 = lv[k * DD + d + 1];
        float m0 = mu[k * DD + d], m1 = mu[k * DD + d + 1];
        float i0 = expf(-l0), i1 = expf(-l1);
        s_cb[p][k >> 1][k & 1] = pack2(-2.0f * i0 * m0, -2.0f * i1 * m1);
        if (l0 != 0.0f || l1 != 0.0f) atomicOr(&s_nz, 1);
    }
    if (t < 80) {                                      // C_k partials: 10 k x 8 parts
        int k = t >> 3, part = t & 7;
        float s = 0.0f;
        #pragma unroll 4
        for (int j = 0; j < 32; j++) {
            int d = part * 32 + j;
            float l = lv[k * DD + d], m = mu[k * DD + d];
            s += expf(-l) * m * m + l + L2PI_F;
        }
        s_Cpart[k][part] = s;
    }

    // ---- stage chunk 0 into buffer 0 (conflict-free mapping) ----
    #pragma unroll
    for (int s8 = 0; s8 < 8; s8++) {
        int i = t + BT * s8;                           // 0..1023
        int r = i >> 3, f4 = i & 7;
        int gr = row0 + r;
        float4 v = make_float4(0.f, 0.f, 0.f, 0.f);
        if (gr < nrows)
            v = *reinterpret_cast<const float4*>(q + (size_t)gr * DD + 4 * f4);
        s_qf[0][4 * f4 + 0][r] = v.x;
        s_qf[0][4 * f4 + 1][r] = v.y;
        s_qf[0][4 * f4 + 2][r] = v.z;
        s_qf[0][4 * f4 + 3][r] = v.w;
    }
    __syncthreads();

    const int fast = (s_nz == 0);
    if (t < KK) {
        float tot = 0.0f;
        #pragma unroll
        for (int j = 0; j < 8; j++) tot += s_Cpart[t][j];
        s_C[t] = __fmaf_rn(-0.5f, tot, logk);
    }
    // (s_C consumed only after the chunk loop's syncs)

    // ---- main loop: S2 = sum q^2 (k-independent), acc_k = sum cB_k * q ----
    ull S2 = 0ull;
    ull acc[KK];
    #pragma unroll
    for (int k = 0; k < KK; k++) acc[k] = 0ull;

    for (int c = 0; c < NCH; c++) {
        int b = c & 1;
        if (c + 1 < NCH) {                             // stage next chunk (overlap)
            int nb = (c + 1) & 1;
            #pragma unroll
            for (int s8 = 0; s8 < 8; s8++) {
                int i = t + BT * s8;
                int r = i >> 3, f4 = i & 7;
                int gr = row0 + r;
                float4 v = make_float4(0.f, 0.f, 0.f, 0.f);
                if (gr < nrows)
                    v = *reinterpret_cast<const float4*>(
                        q + (size_t)gr * DD + (c + 1) * CHD + 4 * f4);
                s_qf[nb][4 * f4 + 0][r] = v.x;
                s_qf[nb][4 * f4 + 1][r] = v.y;
                s_qf[nb][4 * f4 + 2][r] = v.z;
                s_qf[nb][4 * f4 + 3][r] = v.w;
            }
        }

        ull qq[16];
        #pragma unroll
        for (int p = 0; p < 16; p++)
            qq[p] = pack2(s_qf[b][2 * p][t], s_qf[b][2 * p + 1][t]);

        #pragma unroll
        for (int p = 0; p < 16; p++) S2 = fma2(qq[p], qq[p], S2);

        #pragma unroll
        for (int p = 0; p < 16; p++) {
            #pragma unroll
            for (int kp = 0; kp < 5; kp++) {
                ulonglong2 cb = *reinterpret_cast<const ulonglong2*>(
                    &s_cb[c * 16 + p][kp][0]);         // broadcast LDS.128
                acc[2 * kp]     = fma2(cb.x, qq[p], acc[2 * kp]);
                acc[2 * kp + 1] = fma2(cb.y, qq[p], acc[2 * kp + 1]);
            }
        }
        __syncthreads();
    }

    // ---- fused finish (cheap, tolerant) + near-tie flagging ----
    if (row < nrows) {
        float s2f;
        { float lo, hi; unpack2(S2, lo, hi); s2f = lo + hi; }
        float l[KK];
        #pragma unroll
        for (int k = 0; k < KK; k++) {
            float lo, hi; unpack2(acc[k], lo, hi);
            l[k] = __fmaf_rn(-0.5f, (lo + hi) + s2f, s_C[k]);
        }
        float t1 = l[0], t2 = -3.4e38f;
        #pragma unroll
        for (int k = 1; k < KK; k++) {
            float v = l[k];
            if (v > t1) { t2 = t1; t1 = v; } else if (v > t2) t2 = v;
        }
        float e[KK], ssum = 0.0f;
        #pragma unroll
        for (int k = 0; k < KK; k++) { e[k] = __expf(l[k] - t1); ssum += e[k]; }
        float inv = 1.0f / ssum;

        float2* lo2 = reinterpret_cast<float2*>(out_logit + (size_t)row * KK);
        float2* qo2 = reinterpret_cast<float2*>(out_qy    + (size_t)row * KK);
        #pragma unroll
        for (int i = 0; i < KK / 2; i++) {
            lo2[i] = make_float2(l[2 * i], l[2 * i + 1]);
            qo2[i] = make_float2(e[2 * i] * inv, e[2 * i + 1] * inv);
        }
        int best = 0; float bv = l[0];
        #pragma unroll
        for (int k = 1; k < KK; k++) if (l[k] > bv) { bv = l[k]; best = k; }
        out_ind[row] = (float)best;

        if (!fast || (t1 - t2 < MARGIN)) {             // !fast -> exact handles all
            int ix = atomicAdd(&s_cnt, 1);
            s_list[ix] = row;
        }
    }
    __syncthreads();

    // ---- exact fix: bitwise XLA:GPU emulation (round-3 order, proven) ----
    int wid = t >> 5, lane = t & 31;
    int cnt = s_cnt;
    for (int i = wid; i < cnt; i += BT / 32) {
        int rr = s_list[i];
        float l10[KK];
        #pragma unroll 2
        for (int k = 0; k < KK; k++) {
            float W[4];
            #pragma unroll
            for (int j = 0; j < 4; j++) {
                int d0 = 64 * j + 2 * lane;
                float2 qq2 = *reinterpret_cast<const float2*>(q + (size_t)rr * DD + d0);
                float m0 = mu[k * DD + d0], m1 = mu[k * DD + d0 + 1];
                float v0 = lv[k * DD + d0], v1 = lv[k * DD + d0 + 1];
                float e0 = (v0 == 0.0f) ? 1.0f : expf(v0);
                float e1 = (v1 == 0.0f) ? 1.0f : expf(v1);
                float f0 = __fadd_rn(qq2.x, -m0);
                float f1 = __fadd_rn(qq2.y, -m1);
                // u = fl(fl(fl(fl(diff^2)/e^lv)+lv)+L2PI); lv==0 -> == fl(fl(d^2)+L2PI)
                float u0 = __fadd_rn(__fadd_rn(__fdiv_rn(__fmul_rn(f0, f0), e0), v0), L2PI_F);
                float u1 = __fadd_rn(__fadd_rn(__fdiv_rn(__fmul_rn(f1, f1), e1), v1), L2PI_F);
                float s = __fadd_rn(u0, u1);           // s_t = fl(u_even + u_odd)
                s = __fadd_rn(s, __shfl_down_sync(0xffffffffu, s, 16));
                s = __fadd_rn(s, __shfl_down_sync(0xffffffffu, s, 8));
                s = __fadd_rn(s, __shfl_down_sync(0xffffffffu, s, 4));
                s = __fadd_rn(s, __shfl_down_sync(0xffffffffu, s, 2));
                s = __fadd_rn(s, __shfl_down_sync(0xffffffffu, s, 1));
                W[j] = __shfl_sync(0xffffffffu, s, 0);
            }
            float L = __fadd_rn(__fadd_rn(W[0], W[2]), __fadd_rn(W[1], W[3]));
            l10[k] = __fadd_rn(__fmul_rn(-0.5f, L), logk);
        }
        if (lane == 0) {
            float m = l10[0];
            #pragma unroll
            for (int k = 1; k < KK; k++) m = fmaxf(m, l10[k]);
            float e[KK];
            #pragma unroll
            for (int k = 0; k < KK; k++) e[k] = expf(__fadd_rn(l10[k], -m));
            float s0 = __fadd_rn(__fadd_rn(__fadd_rn(e[0], e[8]), e[4]),
                                 __fadd_rn(e[2], e[6]));
            float s1 = __fadd_rn(__fadd_rn(__fadd_rn(e[1], e[9]), e[5]),
                                 __fadd_rn(e[3], e[7]));
            float ssum = __fadd_rn(s0, s1);
            float qv[KK];
            #pragma unroll
            for (int k = 0; k < KK; k++) qv[k] = __fdiv_rn(e[k], ssum);
            #pragma unroll
            for (int k = 0; k < KK; k++) {
                out_logit[(size_t)rr * KK + k] = l10[k];
                out_qy   [(size_t)rr * KK + k] = qv[k];
            }
            int best = 0; float bv = qv[0];
            #pragma unroll
            for (int k = 1; k < KK; k++)
                if (qv[k] > bv) { bv = qv[k]; best = k; }
            out_ind[rr] = (float)best;
        }
    }
}

extern "C" void kernel_launch(void* const* d_in, const int* in_sizes, int n_in,
                              void* d_out, int out_size) {
    const float* q_z = (const float*)d_in[0];   // [B, 256]
    const float* mu  = (const float*)d_in[1];   // [10, 256]
    const float* lv  = (const float*)d_in[2];   // [10, 256]

    int nrows = in_sizes[0] / DD;

    float* out_logit = (float*)d_out;                    // [B, 10]
    float* out_qy    = out_logit + (size_t)nrows * KK;   // [B, 10]
    float* out_ind   = out_qy    + (size_t)nrows * KK;   // [B]

    int grid = (nrows + BT - 1) / BT;                    // 512 blocks
    k_all<<<grid, BT>>>(q_z, mu, lv, out_logit, out_qy, out_ind, nrows);
}

// round 6
// speedup vs baseline: 2.3735x; 1.0262x over previous
#include <cuda_runtime.h>
#include <cstdint>
#include <math.h>

// Problem constants (dataset: B=65536, D=256, K=10)
#define KK 10
#define DD 256
#define BT 32                // 1 warp per block
#define NCH 8                // d-chunks per row
#define CHD 32               // d per chunk
#define QPAD 36              // padded row stride in smem floats (conflict-free .128)
#define MARGIN 0.03f
#define LISTCAP 65536
#define L2PI_F 1.8378770664093453f

typedef unsigned long long ull;

// ---- device globals (no allocation allowed) ----
__device__ __align__(16) ull g_cb[128 * 5 * 2];   // [pair][kpair][e]: -2*e^{-lv}*mu packed (d,d+1)
__device__ float g_Cc[KK];                        // cheap-path constant per k
__device__ int   g_fast;
__device__ int   g_cnt;
__device__ int   g_list[LISTCAP];

// ---------- packed f32x2 helpers ----------
static __device__ __forceinline__ ull pack2(float x, float y) {
    ull r; asm("mov.b64 %0, {%1, %2};" : "=l"(r) : "f"(x), "f"(y)); return r;
}
static __device__ __forceinline__ void unpack2(ull v, float& x, float& y) {
    asm("mov.b64 {%0, %1}, %2;" : "=f"(x), "=f"(y) : "l"(v));
}
static __device__ __forceinline__ ull fma2(ull a, ull b, ull c) {
    ull d; asm("fma.rn.f32x2 %0, %1, %2, %3;" : "=l"(d) : "l"(a), "l"(b), "l"(c)); return d;
}

// ================= kernel 0: prep (once) =================
__global__ void __launch_bounds__(1024)
k_prep(const float* __restrict__ mu, const float* __restrict__ lv) {
    __shared__ int s_nz;
    int t = threadIdx.x;
    if (t == 0) s_nz = 0;
    __syncthreads();

    // cb coefficients: 1280 entries (k,dpair)
    int any = 0;
    for (int i = t; i < KK * 128; i += 1024) {
        int k = i / 128, p = i % 128, d = 2 * p;
        float l0 = lv[k * DD + d], l1 = lv[k * DD + d + 1];
        float m0 = mu[k * DD + d], m1 = mu[k * DD + d + 1];
        float i0 = expf(-l0), i1 = expf(-l1);
        int kp = k >> 1, e = k & 1;
        g_cb[(p * 5 + kp) * 2 + e] = pack2(-2.0f * i0 * m0, -2.0f * i1 * m1);
        if (l0 != 0.0f || l1 != 0.0f) any = 1;
    }
    if (any) atomicOr(&s_nz, 1);

    // C_k: warp w handles k=w (first 10 warps)
    int w = t >> 5, lane = t & 31;
    if (w < KK) {
        float s = 0.0f;
        #pragma unroll
        for (int j = 0; j < 8; j++) {
            int d = lane + 32 * j;
            float l = lv[w * DD + d], m = mu[w * DD + d];
            s += expf(-l) * m * m + l + L2PI_F;
        }
        #pragma unroll
        for (int off = 16; off > 0; off >>= 1)
            s += __shfl_xor_sync(0xffffffffu, s, off);
        if (lane == 0) {
            float logk = (float)log((double)(1.0f / (float)KK));
            g_Cc[w] = __fmaf_rn(-0.5f, s, logk);
        }
    }
    __syncthreads();
    if (t == 0) { g_fast = (s_nz == 0); g_cnt = 0; }
}

// ================= kernel 1: cheap logits + finish + flagging =================
__global__ void __launch_bounds__(BT)
k_main(const float* __restrict__ q,
       float* __restrict__ out_logit, float* __restrict__ out_qy,
       float* __restrict__ out_ind, int nrows)
{
    __shared__ __align__(16) ull   s_cb[128 * 5 * 2];     // 10240 B
    __shared__ __align__(16) float s_q[BT][QPAD];         // 4608 B
    __shared__ float s_C[KK];

    const int t   = threadIdx.x;
    const int row = blockIdx.x * BT + t;

    // load coefficient table (coalesced LDG.128 -> STS.128)
    {
        const ulonglong2* src = reinterpret_cast<const ulonglong2*>(g_cb);
        ulonglong2* dst = reinterpret_cast<ulonglong2*>(s_cb);
        #pragma unroll
        for (int i = 0; i < 640 / BT; i++) dst[t + BT * i] = src[t + BT * i];
    }
    if (t < KK) s_C[t] = g_Cc[t];
    const int fast = g_fast;

    // stage chunk 0
    {
        #pragma unroll
        for (int s8 = 0; s8 < 8; s8++) {
            int i = t + BT * s8, r = i >> 3, f4 = i & 7;
            int gr = blockIdx.x * BT + r;
            float4 v = make_float4(0.f, 0.f, 0.f, 0.f);
            if (gr < nrows)
                v = *reinterpret_cast<const float4*>(q + (size_t)gr * DD + 4 * f4);
            *reinterpret_cast<float4*>(&s_q[r][4 * f4]) = v;
        }
    }
    __syncwarp();

    ull S2 = 0ull;
    ull acc[KK];
    #pragma unroll
    for (int k = 0; k < KK; k++) acc[k] = 0ull;

    for (int c = 0; c < NCH; c++) {
        // prefetch next chunk into registers (overlaps with compute)
        float4 pf[8];
        if (c + 1 < NCH) {
            #pragma unroll
            for (int s8 = 0; s8 < 8; s8++) {
                int i = t + BT * s8, r = i >> 3, f4 = i & 7;
                int gr = blockIdx.x * BT + r;
                pf[s8] = make_float4(0.f, 0.f, 0.f, 0.f);
                if (gr < nrows)
                    pf[s8] = *reinterpret_cast<const float4*>(
                        q + (size_t)gr * DD + (c + 1) * CHD + 4 * f4);
            }
        }

        // own row chunk: 8 conflict-free LDS.128
        ull qq[16];
        #pragma unroll
        for (int j = 0; j < 8; j++) {
            float4 v = *reinterpret_cast<const float4*>(&s_q[t][4 * j]);
            qq[2 * j]     = pack2(v.x, v.y);
            qq[2 * j + 1] = pack2(v.z, v.w);
        }

        #pragma unroll
        for (int p = 0; p < 16; p++) S2 = fma2(qq[p], qq[p], S2);

        #pragma unroll
        for (int p = 0; p < 16; p++) {
            int cp = c * 16 + p;
            #pragma unroll
            for (int kp = 0; kp < 5; kp++) {
                ulonglong2 cb = *reinterpret_cast<const ulonglong2*>(
                    &s_cb[(cp * 5 + kp) * 2]);        // broadcast LDS.128
                acc[2 * kp]     = fma2(cb.x, qq[p], acc[2 * kp]);
                acc[2 * kp + 1] = fma2(cb.y, qq[p], acc[2 * kp + 1]);
            }
        }

        if (c + 1 < NCH) {
            __syncwarp();
            #pragma unroll
            for (int s8 = 0; s8 < 8; s8++) {
                int i = t + BT * s8, r = i >> 3, f4 = i & 7;
                *reinterpret_cast<float4*>(&s_q[r][4 * f4]) = pf[s8];
            }
            __syncwarp();
        }
    }

    // ---- finish (cheap, tolerant) + near-tie flagging ----
    if (row < nrows) {
        float s2f;
        { float lo, hi; unpack2(S2, lo, hi); s2f = lo + hi; }
        float l[KK];
        #pragma unroll
        for (int k = 0; k < KK; k++) {
            float lo, hi; unpack2(acc[k], lo, hi);
            l[k] = __fmaf_rn(-0.5f, (lo + hi) + s2f, s_C[k]);
        }
        float t1 = l[0], t2 = -3.4e38f;
        #pragma unroll
        for (int k = 1; k < KK; k++) {
            float v = l[k];
            if (v > t1) { t2 = t1; t1 = v; } else if (v > t2) t2 = v;
        }
        float e[KK], ssum = 0.0f;
        #pragma unroll
        for (int k = 0; k < KK; k++) { e[k] = __expf(l[k] - t1); ssum += e[k]; }
        float inv = 1.0f / ssum;

        float2* lo2 = reinterpret_cast<float2*>(out_logit + (size_t)row * KK);
        float2* qo2 = reinterpret_cast<float2*>(out_qy    + (size_t)row * KK);
        #pragma unroll
        for (int i = 0; i < KK / 2; i++) {
            lo2[i] = make_float2(l[2 * i], l[2 * i + 1]);
            qo2[i] = make_float2(e[2 * i] * inv, e[2 * i + 1] * inv);
        }
        int best = 0; float bv = l[0];
        #pragma unroll
        for (int k = 1; k < KK; k++) if (l[k] > bv) { bv = l[k]; best = k; }
        out_ind[row] = (float)best;

        if (!fast || (t1 - t2 < MARGIN)) {
            int ix = atomicAdd(&g_cnt, 1);
            if (ix < LISTCAP) g_list[ix] = row;
        }
    }
}

// ================= kernel 2: exact fix (bitwise XLA:GPU order, proven) =================
__global__ void __launch_bounds__(128)
k_fix(const float* __restrict__ q, const float* __restrict__ mu,
      const float* __restrict__ lv,
      float* __restrict__ out_logit, float* __restrict__ out_qy,
      float* __restrict__ out_ind)
{
    int lane = threadIdx.x & 31;
    int gw   = (blockIdx.x * blockDim.x + threadIdx.x) >> 5;
    int nw   = (gridDim.x * blockDim.x) >> 5;
    int n    = g_cnt; if (n > LISTCAP) n = LISTCAP;
    const float logk = (float)log((double)(1.0f / (float)KK));

    for (int i = gw; i < n; i += nw) {
        int rr = g_list[i];
        float l10[KK];
        #pragma unroll 2
        for (int k = 0; k < KK; k++) {
            float W[4];
            #pragma unroll
            for (int j = 0; j < 4; j++) {
                int d0 = 64 * j + 2 * lane;
                float2 qq2 = *reinterpret_cast<const float2*>(q + (size_t)rr * DD + d0);
                float m0 = mu[k * DD + d0], m1 = mu[k * DD + d0 + 1];
                float v0 = lv[k * DD + d0], v1 = lv[k * DD + d0 + 1];
                float e0 = (v0 == 0.0f) ? 1.0f : expf(v0);
                float e1 = (v1 == 0.0f) ? 1.0f : expf(v1);
                float f0 = __fadd_rn(qq2.x, -m0);
                float f1 = __fadd_rn(qq2.y, -m1);
                // u = fl(fl(fl(fl(diff^2)/e^lv)+lv)+L2PI); lv==0 -> fl(fl(d^2)+L2PI)
                float u0 = __fadd_rn(__fadd_rn(__fdiv_rn(__fmul_rn(f0, f0), e0), v0), L2PI_F);
                float u1 = __fadd_rn(__fadd_rn(__fdiv_rn(__fmul_rn(f1, f1), e1), v1), L2PI_F);
                float s = __fadd_rn(u0, u1);
                s = __fadd_rn(s, __shfl_down_sync(0xffffffffu, s, 16));
                s = __fadd_rn(s, __shfl_down_sync(0xffffffffu, s, 8));
                s = __fadd_rn(s, __shfl_down_sync(0xffffffffu, s, 4));
                s = __fadd_rn(s, __shfl_down_sync(0xffffffffu, s, 2));
                s = __fadd_rn(s, __shfl_down_sync(0xffffffffu, s, 1));
                W[j] = __shfl_sync(0xffffffffu, s, 0);
            }
            float L = __fadd_rn(__fadd_rn(W[0], W[2]), __fadd_rn(W[1], W[3]));
            l10[k] = __fadd_rn(__fmul_rn(-0.5f, L), logk);
        }
        if (lane == 0) {
            float m = l10[0];
            #pragma unroll
            for (int k = 1; k < KK; k++) m = fmaxf(m, l10[k]);
            float e[KK];
            #pragma unroll
            for (int k = 0; k < KK; k++) e[k] = expf(__fadd_rn(l10[k], -m));
            float s0 = __fadd_rn(__fadd_rn(__fadd_rn(e[0], e[8]), e[4]),
                                 __fadd_rn(e[2], e[6]));
            float s1 = __fadd_rn(__fadd_rn(__fadd_rn(e[1], e[9]), e[5]),
                                 __fadd_rn(e[3], e[7]));
            float ssum = __fadd_rn(s0, s1);
            float qv[KK];
            #pragma unroll
            for (int k = 0; k < KK; k++) qv[k] = __fdiv_rn(e[k], ssum);
            #pragma unroll
            for (int k = 0; k < KK; k++) {
                out_logit[(size_t)rr * KK + k] = l10[k];
                out_qy   [(size_t)rr * KK + k] = qv[k];
            }
            int best = 0; float bv = qv[0];
            #pragma unroll
            for (int k = 1; k < KK; k++)
                if (qv[k] > bv) { bv = qv[k]; best = k; }
            out_ind[rr] = (float)best;
        }
    }
}

extern "C" void kernel_launch(void* const* d_in, const int* in_sizes, int n_in,
                              void* d_out, int out_size) {
    const float* q_z = (const float*)d_in[0];   // [B, 256]
    const float* mu  = (const float*)d_in[1];   // [10, 256]
    const float* lv  = (const float*)d_in[2];   // [10, 256]

    int nrows = in_sizes[0] / DD;

    float* out_logit = (float*)d_out;                    // [B, 10]
    float* out_qy    = out_logit + (size_t)nrows * KK;   // [B, 10]
    float* out_ind   = out_qy    + (size_t)nrows * KK;   // [B]

    k_prep<<<1, 1024>>>(mu, lv);
    k_main<<<(nrows + BT - 1) / BT, BT>>>(q_z, out_logit, out_qy, out_ind, nrows);
    k_fix<<<128, 128>>>(q_z, mu, lv, out_logit, out_qy, out_ind);
}

// round 7
// speedup vs baseline: 3.1026x; 1.3072x over previous
#include <cuda_runtime.h>
#include <cstdint>
#include <math.h>

// Problem constants (dataset: B=65536, D=256, K=10)
#define KK 10
#define DD 256
#define RPW 8                 // rows per warp (4 threads per row)
#define WPB 8                 // warps per block
#define RPB 64                // rows per block
#define MARGIN 0.03f
#define LISTCAP 65536
#define L2PI_F 1.8378770664093453f

typedef unsigned long long ull;

// ---- device globals (no allocation allowed) ----
// cb layout (ull2 = 16B units): idx16 = ((2g+h)*5 + kp)*4 + s  for pair p = 2s+8g+h
__device__ __align__(16) ull g_cb[640 * 2];
__device__ float g_Cc[KK];
__device__ int   g_nzarr[KK];
__device__ int   g_cnt;
__device__ int   g_list[LISTCAP];

// ---------- packed f32x2 helpers ----------
static __device__ __forceinline__ ull pack2(float x, float y) {
    ull r; asm("mov.b64 %0, {%1, %2};" : "=l"(r) : "f"(x), "f"(y)); return r;
}
static __device__ __forceinline__ void unpack2(ull v, float& x, float& y) {
    asm("mov.b64 {%0, %1}, %2;" : "=f"(x), "=f"(y) : "l"(v));
}
static __device__ __forceinline__ ull fma2(ull a, ull b, ull c) {
    ull d; asm("fma.rn.f32x2 %0, %1, %2, %3;" : "=l"(d) : "l"(a), "l"(b), "l"(c)); return d;
}
static __device__ __forceinline__ ull add2(ull a, ull b) {
    ull d; asm("add.rn.f32x2 %0, %1, %2;" : "=l"(d) : "l"(a), "l"(b)); return d;
}

// ================= kernel 0: prep — one block per k =================
__global__ void __launch_bounds__(128)
k_prep(const float* __restrict__ mu, const float* __restrict__ lv) {
    __shared__ float s_part[4];
    __shared__ int   s_nz[4];
    int k = blockIdx.x;         // 0..9
    int t = threadIdx.x;        // pair index p = t (0..127)
    int d = 2 * t;

    float l0 = lv[k * DD + d], l1 = lv[k * DD + d + 1];
    float m0 = mu[k * DD + d], m1 = mu[k * DD + d + 1];
    float i0 = expf(-l0), i1 = expf(-l1);

    // scatter cb into the 4-sub interleaved layout
    int h = t & 1, sg = t >> 1, s = sg & 3, g = sg >> 2;
    int idx = ((((2 * g + h) * 5 + (k >> 1)) * 4 + s) * 2) + (k & 1);
    g_cb[idx] = pack2(-2.0f * i0 * m0, -2.0f * i1 * m1);

    // C_k partial: e^{-lv} mu^2 + lv + L2PI for both d's
    float cs = (__fmaf_rn(i0 * m0, m0, l0) + L2PI_F)
             + (__fmaf_rn(i1 * m1, m1, l1) + L2PI_F);
    int nz = (l0 != 0.0f || l1 != 0.0f) ? 1 : 0;

    int lane = t & 31, w = t >> 5;
    #pragma unroll
    for (int off = 16; off > 0; off >>= 1) {
        cs += __shfl_xor_sync(0xffffffffu, cs, off);
        nz |= __shfl_xor_sync(0xffffffffu, nz, off);
    }
    if (lane == 0) { s_part[w] = cs; s_nz[w] = nz; }
    __syncthreads();
    if (t == 0) {
        float tot = (s_part[0] + s_part[1]) + (s_part[2] + s_part[3]);
        float logk = (float)log((double)(1.0f / (float)KK));
        g_Cc[k]    = __fmaf_rn(-0.5f, tot, logk);
        g_nzarr[k] = s_nz[0] | s_nz[1] | s_nz[2] | s_nz[3];
        if (k == 0) g_cnt = 0;
    }
}

// ================= kernel 1: cheap logits + finish + flagging =================
__global__ void __launch_bounds__(256, 3)
k_main(const float* __restrict__ q,
       float* __restrict__ out_logit, float* __restrict__ out_qy,
       float* __restrict__ out_ind, int nrows)
{
    __shared__ __align__(16) ulonglong2 s_cb[640];   // 10240 B
    __shared__ float s_C[KK];
    __shared__ int   s_fast;

    int t = threadIdx.x;
    {
        const ulonglong2* src = reinterpret_cast<const ulonglong2*>(g_cb);
        #pragma unroll
        for (int i = 0; i < 3; i++) {
            int ix = t + 256 * i;
            if (ix < 640) s_cb[ix] = src[ix];
        }
    }
    if (t < KK) s_C[t] = g_Cc[t];
    if (t == 0) {
        int nz = 0;
        #pragma unroll
        for (int j = 0; j < KK; j++) nz |= g_nzarr[j];
        s_fast = (nz == 0);
    }
    __syncthreads();

    const int lane = t & 31, warp = t >> 5;
    const int s = lane & 3, r = lane >> 2;
    const int row = blockIdx.x * RPB + warp * RPW + r;
    const bool valid = (row < nrows);
    const float4* qp = reinterpret_cast<const float4*>(
        q + (size_t)(valid ? row : 0) * DD + 4 * s);

    ull acc[KK];
    #pragma unroll
    for (int k = 0; k < KK; k++) acc[k] = 0ull;
    ull S2a = 0ull, S2b = 0ull;

    float4 nv = __ldg(qp);                  // granule g=0 (d = 4s+16g)
    #pragma unroll
    for (int g = 0; g < 16; g++) {
        float4 v = nv;
        if (g + 1 < 16) nv = __ldg(qp + 4 * (g + 1));   // +16 floats
        ull qa = pack2(v.x, v.y);           // pair p = 2s+8g   (h=0)
        ull qb = pack2(v.z, v.w);           // pair p = 2s+8g+1 (h=1)
        S2a = fma2(qa, qa, S2a);
        S2b = fma2(qb, qb, S2b);
        const int b0 = (2 * g + 0) * 5 * 4 + s;
        const int b1 = (2 * g + 1) * 5 * 4 + s;
        #pragma unroll
        for (int kp = 0; kp < 5; kp++) {
            ulonglong2 c0 = s_cb[b0 + 4 * kp];   // 64B-span LDS.128, 1 wavefront
            acc[2 * kp]     = fma2(c0.x, qa, acc[2 * kp]);
            acc[2 * kp + 1] = fma2(c0.y, qa, acc[2 * kp + 1]);
            ulonglong2 c1 = s_cb[b1 + 4 * kp];
            acc[2 * kp]     = fma2(c1.x, qb, acc[2 * kp]);
            acc[2 * kp + 1] = fma2(c1.y, qb, acc[2 * kp + 1]);
        }
    }
    ull S2 = add2(S2a, S2b);

    // reduce across the 4 sub-lanes of each row (offsets 1, 2)
    #pragma unroll
    for (int k = 0; k < KK; k++) {
        acc[k] = add2(acc[k], __shfl_xor_sync(0xffffffffu, acc[k], 1));
        acc[k] = add2(acc[k], __shfl_xor_sync(0xffffffffu, acc[k], 2));
    }
    S2 = add2(S2, __shfl_xor_sync(0xffffffffu, S2, 1));
    S2 = add2(S2, __shfl_xor_sync(0xffffffffu, S2, 2));

    if (s == 0 && valid) {
        float s2f;
        { float lo, hi; unpack2(S2, lo, hi); s2f = lo + hi; }
        float l[KK];
        #pragma unroll
        for (int k = 0; k < KK; k++) {
            float lo, hi; unpack2(acc[k], lo, hi);
            l[k] = __fmaf_rn(-0.5f, (lo + hi) + s2f, s_C[k]);
        }
        float t1 = l[0], t2 = -3.4e38f;
        #pragma unroll
        for (int k = 1; k < KK; k++) {
            float v = l[k];
            if (v > t1) { t2 = t1; t1 = v; } else if (v > t2) t2 = v;
        }
        float e[KK], ssum = 0.0f;
        #pragma unroll
        for (int k = 0; k < KK; k++) { e[k] = __expf(l[k] - t1); ssum += e[k]; }
        float inv = 1.0f / ssum;

        float2* lo2 = reinterpret_cast<float2*>(out_logit + (size_t)row * KK);
        float2* qo2 = reinterpret_cast<float2*>(out_qy    + (size_t)row * KK);
        #pragma unroll
        for (int i = 0; i < KK / 2; i++) {
            lo2[i] = make_float2(l[2 * i], l[2 * i + 1]);
            qo2[i] = make_float2(e[2 * i] * inv, e[2 * i + 1] * inv);
        }
        int best = 0; float bv = l[0];
        #pragma unroll
        for (int k = 1; k < KK; k++) if (l[k] > bv) { bv = l[k]; best = k; }
        out_ind[row] = (float)best;

        if (!s_fast || (t1 - t2 < MARGIN)) {   // !fast -> exact path redoes all
            int ix = atomicAdd(&g_cnt, 1);
            if (ix < LISTCAP) g_list[ix] = row;
        }
    }
}

// ================= kernel 2: exact fix (bitwise XLA:GPU order, proven) =================
__global__ void __launch_bounds__(128)
k_fix(const float* __restrict__ q, const float* __restrict__ mu,
      const float* __restrict__ lv,
      float* __restrict__ out_logit, float* __restrict__ out_qy,
      float* __restrict__ out_ind)
{
    int lane = threadIdx.x & 31;
    int gw   = (blockIdx.x * blockDim.x + threadIdx.x) >> 5;
    int nw   = (gridDim.x * blockDim.x) >> 5;
    int n    = g_cnt; if (n > LISTCAP) n = LISTCAP;
    const float logk = (float)log((double)(1.0f / (float)KK));

    for (int i = gw; i < n; i += nw) {
        int rr = g_list[i];
        float l10[KK];
        #pragma unroll 2
        for (int k = 0; k < KK; k++) {
            float W[4];
            #pragma unroll
            for (int j = 0; j < 4; j++) {
                int d0 = 64 * j + 2 * lane;
                float2 qq2 = *reinterpret_cast<const float2*>(q + (size_t)rr * DD + d0);
                float m0 = mu[k * DD + d0], m1 = mu[k * DD + d0 + 1];
                float v0 = lv[k * DD + d0], v1 = lv[k * DD + d0 + 1];
                float e0 = (v0 == 0.0f) ? 1.0f : expf(v0);
                float e1 = (v1 == 0.0f) ? 1.0f : expf(v1);
                float f0 = __fadd_rn(qq2.x, -m0);
                float f1 = __fadd_rn(qq2.y, -m1);
                // u = fl(fl(fl(fl(diff^2)/e^lv)+lv)+L2PI); lv==0 -> fl(fl(d^2)+L2PI)
                float u0 = __fadd_rn(__fadd_rn(__fdiv_rn(__fmul_rn(f0, f0), e0), v0), L2PI_F);
                float u1 = __fadd_rn(__fadd_rn(__fdiv_rn(__fmul_rn(f1, f1), e1), v1), L2PI_F);
                float ss = __fadd_rn(u0, u1);           // s_t = fl(u_even + u_odd)
                ss = __fadd_rn(ss, __shfl_down_sync(0xffffffffu, ss, 16));
                ss = __fadd_rn(ss, __shfl_down_sync(0xffffffffu, ss, 8));
                ss = __fadd_rn(ss, __shfl_down_sync(0xffffffffu, ss, 4));
                ss = __fadd_rn(ss, __shfl_down_sync(0xffffffffu, ss, 2));
                ss = __fadd_rn(ss, __shfl_down_sync(0xffffffffu, ss, 1));
                W[j] = __shfl_sync(0xffffffffu, ss, 0);
            }
            float L = __fadd_rn(__fadd_rn(W[0], W[2]), __fadd_rn(W[1], W[3]));
            l10[k] = __fadd_rn(__fmul_rn(-0.5f, L), logk);
        }
        if (lane == 0) {
            float m = l10[0];
            #pragma unroll
            for (int k = 1; k < KK; k++) m = fmaxf(m, l10[k]);
            float e[KK];
            #pragma unroll
            for (int k = 0; k < KK; k++) e[k] = expf(__fadd_rn(l10[k], -m));
            float s0 = __fadd_rn(__fadd_rn(__fadd_rn(e[0], e[8]), e[4]),
                                 __fadd_rn(e[2], e[6]));
            float s1 = __fadd_rn(__fadd_rn(__fadd_rn(e[1], e[9]), e[5]),
                                 __fadd_rn(e[3], e[7]));
            float ssum = __fadd_rn(s0, s1);
            float qv[KK];
            #pragma unroll
            for (int k = 0; k < KK; k++) qv[k] = __fdiv_rn(e[k], ssum);
            #pragma unroll
            for (int k = 0; k < KK; k++) {
                out_logit[(size_t)rr * KK + k] = l10[k];
                out_qy   [(size_t)rr * KK + k] = qv[k];
            }
            int best = 0; float bv = qv[0];
            #pragma unroll
            for (int k = 1; k < KK; k++)
                if (qv[k] > bv) { bv = qv[k]; best = k; }
            out_ind[rr] = (float)best;
        }
    }
}

extern "C" void kernel_launch(void* const* d_in, const int* in_sizes, int n_in,
                              void* d_out, int out_size) {
    const float* q_z = (const float*)d_in[0];   // [B, 256]
    const float* mu  = (const float*)d_in[1];   // [10, 256]
    const float* lv  = (const float*)d_in[2];   // [10, 256]

    int nrows = in_sizes[0] / DD;

    float* out_logit = (float*)d_out;                    // [B, 10]
    float* out_qy    = out_logit + (size_t)nrows * KK;   // [B, 10]
    float* out_ind   = out_qy    + (size_t)nrows * KK;   // [B]

    k_prep<<<KK, 128>>>(mu, lv);
    k_main<<<(nrows + RPB - 1) / RPB, 256>>>(q_z, out_logit, out_qy, out_ind, nrows);
    k_fix<<<256, 128>>>(q_z, mu, lv, out_logit, out_qy, out_ind);
}